// round 8
// baseline (speedup 1.0000x reference)
#include <cuda_runtime.h>

// AdderNet: out[n,h,w,f] = sum_{dh,dw,c} |Xpad[n,h+dh-1,w+dw-1,c] - F[f,dh,dw,c]|
// X [8,32,32,32] f32 NHWC, F [64,3,3,32] f32, out [8,32,32,64] f32.
//
// R8: LSU-pressure fix. Thread tile 4px x 2f -> 12 loads per 96 elem-ops.
// Grid (256 nh, 4 fq) = 1024 CTAs, block 64 = wq(8) x fg(8) -> 6.7 CTA/SM,
// balance 1.04. X in smem (swizzle s = r*9+q, wp = 4q+r: 6 conflict-free
// 128B-contiguous loads). Filters via LDG, L1D-resident.

#define XS_F4 (3 * 8 * 36)          // 864 float4
#define SMEM_BYTES (XS_F4 * 16)     // 13,824 B

typedef unsigned long long u64;

__device__ __forceinline__ u64 ffma2(u64 a, u64 b, u64 c) {
    u64 r;
    asm("fma.rn.f32x2 %0, %1, %2, %3;" : "=l"(r) : "l"(a), "l"(b), "l"(c));
    return r;
}
__device__ __forceinline__ u64 fadd2(u64 a, u64 b) {
    u64 r;
    asm("add.rn.f32x2 %0, %1, %2;" : "=l"(r) : "l"(a), "l"(b));
    return r;
}

__global__ __launch_bounds__(64, 7)
void adder_layer_kernel(const float* __restrict__ X,
                        const float* __restrict__ Fw,
                        float* __restrict__ out) {
    extern __shared__ __align__(16) float4 smem4[];
    float4* Xs4 = smem4;              // [(dh*8 + c4)*36 + s], s = r*9 + q, wp = 4q + r

    const int tid = threadIdx.x;
    const int nh = blockIdx.x;        // n*32 + h
    const int fbase = blockIdx.y * 16;
    const int n = nh >> 5;
    const int h = nh & 31;

    // ---- X fill: 3 rows, swizzled, zero-padded (864 float4 / 64 thr) ----
    const float4* Xg4 = reinterpret_cast<const float4*>(X);
    for (int i = tid; i < XS_F4; i += 64) {
        int c4 = i & 7;
        int t = i >> 3;
        int s = t % 36;
        int dh = t / 36;
        int q = s % 9, r = s / 9;
        int wp = 4 * q + r;
        int row = h - 1 + dh;
        int w = wp - 1;
        float4 v = make_float4(0.f, 0.f, 0.f, 0.f);
        if (row >= 0 && row < 32 && w >= 0 && w < 32)
            v = Xg4[(((n * 32) + row) * 32 + w) * 8 + c4];
        Xs4[(dh * 8 + c4) * 36 + s] = v;
    }
    __syncthreads();

    const int wq = tid & 7;           // pixels w = 4wq .. 4wq+3
    const int fg = tid >> 3;          // 0..7 -> filters fbase+2fg, fbase+2fg+1

    const u64 NEG1 = 0xBF800000BF800000ULL;
    const u64 ABSM = 0x7FFFFFFF7FFFFFFFULL;

    u64 acc[2][4];                    // [filter][pixel]
    #pragma unroll
    for (int fi = 0; fi < 2; fi++)
        #pragma unroll
        for (int p = 0; p < 4; p++) acc[fi][p] = 0ull;

    const ulonglong2* Xu = reinterpret_cast<const ulonglong2*>(Xs4);
    const ulonglong2* __restrict__ Fg = reinterpret_cast<const ulonglong2*>(Fw);
    const ulonglong2* __restrict__ Fb0 = Fg + (fbase + 2 * fg) * 72;  // filter even
    const ulonglong2* __restrict__ Fb1 = Fb0 + 72;                    // filter odd

    #pragma unroll 4
    for (int kk = 0; kk < 24; kk++) {
        const int dh = kk >> 3;
        const int c4 = kk & 7;
        const int foff = dh * 24 + c4;

        // x: 4 channels at wp = 4wq + k, k = 0..5 (one 128B wavefront each)
        const ulonglong2* xr = Xu + kk * 36 + wq;
        ulonglong2 x0 = xr[0];        // s = wq        wp = 4wq
        ulonglong2 x1 = xr[9];        // s = 9+wq      wp = 4wq+1
        ulonglong2 x2 = xr[18];       //               wp = 4wq+2
        ulonglong2 x3 = xr[27];       //               wp = 4wq+3
        ulonglong2 x4 = xr[1];        // s = wq+1      wp = 4wq+4
        ulonglong2 x5 = xr[10];       // s = 9+wq+1    wp = 4wq+5

        // filter taps (L1-resident LDG), 2 filters x 3 dw
        ulonglong2 t00 = __ldg(Fb0 + foff);
        ulonglong2 t01 = __ldg(Fb0 + foff + 8);
        ulonglong2 t02 = __ldg(Fb0 + foff + 16);
        ulonglong2 t10 = __ldg(Fb1 + foff);
        ulonglong2 t11 = __ldg(Fb1 + foff + 8);
        ulonglong2 t12 = __ldg(Fb1 + foff + 16);

        const ulonglong2 xv[6] = {x0, x1, x2, x3, x4, x5};

        #pragma unroll
        for (int p = 0; p < 4; p++) {
            const ulonglong2 xa = xv[p];
            const ulonglong2 xb = xv[p + 1];
            const ulonglong2 xc = xv[p + 2];
            // filter 0 (even)
            acc[0][p] = fadd2(acc[0][p], ffma2(t00.x, NEG1, xa.x) & ABSM);
            acc[0][p] = fadd2(acc[0][p], ffma2(t00.y, NEG1, xa.y) & ABSM);
            acc[0][p] = fadd2(acc[0][p], ffma2(t01.x, NEG1, xb.x) & ABSM);
            acc[0][p] = fadd2(acc[0][p], ffma2(t01.y, NEG1, xb.y) & ABSM);
            acc[0][p] = fadd2(acc[0][p], ffma2(t02.x, NEG1, xc.x) & ABSM);
            acc[0][p] = fadd2(acc[0][p], ffma2(t02.y, NEG1, xc.y) & ABSM);
            // filter 1 (odd)
            acc[1][p] = fadd2(acc[1][p], ffma2(t10.x, NEG1, xa.x) & ABSM);
            acc[1][p] = fadd2(acc[1][p], ffma2(t10.y, NEG1, xa.y) & ABSM);
            acc[1][p] = fadd2(acc[1][p], ffma2(t11.x, NEG1, xb.x) & ABSM);
            acc[1][p] = fadd2(acc[1][p], ffma2(t11.y, NEG1, xb.y) & ABSM);
            acc[1][p] = fadd2(acc[1][p], ffma2(t12.x, NEG1, xc.x) & ABSM);
            acc[1][p] = fadd2(acc[1][p], ffma2(t12.y, NEG1, xc.y) & ABSM);
        }
    }

    // ---- Epilogue: horizontal add of packed lanes, float2 store per pixel ----
    #pragma unroll
    for (int p = 0; p < 4; p++) {
        u64 a0 = acc[0][p], a1 = acc[1][p];
        float r0 = __uint_as_float((unsigned)a0) + __uint_as_float((unsigned)(a0 >> 32));
        float r1 = __uint_as_float((unsigned)a1) + __uint_as_float((unsigned)(a1 >> 32));
        *reinterpret_cast<float2*>(
            out + ((nh * 32) + 4 * wq + p) * 64 + fbase + 2 * fg) = make_float2(r0, r1);
    }
}

extern "C" void kernel_launch(void* const* d_in, const int* in_sizes, int n_in,
                              void* d_out, int out_size) {
    const float* X = (const float*)d_in[0];
    const float* Fw = (const float*)d_in[1];
    float* out = (float*)d_out;

    cudaFuncSetAttribute(adder_layer_kernel,
                         cudaFuncAttributeMaxDynamicSharedMemorySize, SMEM_BYTES);
    dim3 grid(256, 4);
    adder_layer_kernel<<<grid, 64, SMEM_BYTES>>>(X, Fw, out);
}

// round 9
// speedup vs baseline: 1.5607x; 1.5607x over previous
#include <cuda_runtime.h>

// AdderNet: out[n,h,w,f] = sum_{dh,dw,c} |Xpad[n,h+dh-1,w+dw-1,c] - F[f,dh,dw,c]|
// X [8,32,32,32] f32 NHWC, F [64,3,3,32] f32, out [8,32,32,64] f32.
//
// R9: 4px x 2f register tile (LSU:issue balanced, 12 loads per 192 math instrs),
// written straight-line (no staging arrays, unroll 2) to avoid R8's codegen bloat.
// Grid (256 nh, 4 fq) = 1024 CTAs, block 64 = wq(8) x fp(8).
// X smem swizzle s = r*9+q (wp = 4q+r): all 6 x-loads 128B-contiguous across wq.
// Filters via LDG, L1D-resident.

#define XS_F4 (3 * 8 * 36)          // 864 float4
#define SMEM_BYTES (XS_F4 * 16)     // 13,824 B

typedef unsigned long long u64;

__device__ __forceinline__ u64 ffma2(u64 a, u64 b, u64 c) {
    u64 r;
    asm("fma.rn.f32x2 %0, %1, %2, %3;" : "=l"(r) : "l"(a), "l"(b), "l"(c));
    return r;
}
__device__ __forceinline__ u64 fadd2(u64 a, u64 b) {
    u64 r;
    asm("add.rn.f32x2 %0, %1, %2;" : "=l"(r) : "l"(a), "l"(b));
    return r;
}

// acc += |x - t|  over one packed channel-pair (both u64 halves of a 16B chunk)
#define UPD(acc, t, xa)                                               \
    acc = fadd2(acc, ffma2((t).x, NEG1, (xa).x) & ABSM);              \
    acc = fadd2(acc, ffma2((t).y, NEG1, (xa).y) & ABSM)

__global__ __launch_bounds__(64, 8)
void adder_layer_kernel(const float* __restrict__ X,
                        const float* __restrict__ Fw,
                        float* __restrict__ out) {
    extern __shared__ __align__(16) float4 smem4[];
    float4* Xs4 = smem4;              // [(dh*8 + c4)*36 + s], s = r*9 + q, wp = 4q + r

    const int tid = threadIdx.x;
    const int nh = blockIdx.x;        // n*32 + h
    const int fbase = blockIdx.y * 16;
    const int n = nh >> 5;
    const int h = nh & 31;

    // ---- X fill: 3 rows, swizzled, zero-padded ----
    const float4* Xg4 = reinterpret_cast<const float4*>(X);
    for (int i = tid; i < XS_F4; i += 64) {
        int c4 = i & 7;
        int t = i >> 3;
        int s = t % 36;
        int dh = t / 36;
        int q = s % 9, r = s / 9;
        int wp = 4 * q + r;
        int row = h - 1 + dh;
        int w = wp - 1;
        float4 v = make_float4(0.f, 0.f, 0.f, 0.f);
        if (row >= 0 && row < 32 && w >= 0 && w < 32)
            v = Xg4[(((n * 32) + row) * 32 + w) * 8 + c4];
        Xs4[(dh * 8 + c4) * 36 + s] = v;
    }
    __syncthreads();

    const int wq = tid & 7;           // pixels w = 4wq .. 4wq+3
    const int fp = tid >> 3;          // 0..7 -> filters fbase+2fp, fbase+2fp+1

    const u64 NEG1 = 0xBF800000BF800000ULL;
    const u64 ABSM = 0x7FFFFFFF7FFFFFFFULL;

    u64 a00 = 0, a01 = 0, a02 = 0, a03 = 0;   // filter even, pixels 0..3
    u64 a10 = 0, a11 = 0, a12 = 0, a13 = 0;   // filter odd

    const ulonglong2* Xu = reinterpret_cast<const ulonglong2*>(Xs4);
    const ulonglong2* __restrict__ Fg = reinterpret_cast<const ulonglong2*>(Fw);
    const ulonglong2* __restrict__ Fb0 = Fg + (fbase + 2 * fp) * 72;
    const ulonglong2* __restrict__ Fb1 = Fb0 + 72;

    #pragma unroll 2
    for (int kk = 0; kk < 24; kk++) {
        const int dh = kk >> 3;
        const int c4 = kk & 7;
        const int foff = dh * 24 + c4;

        // filter taps (L1-resident LDG), 2 filters x 3 dw
        ulonglong2 t00 = __ldg(Fb0 + foff);
        ulonglong2 t01 = __ldg(Fb0 + foff + 8);
        ulonglong2 t02 = __ldg(Fb0 + foff + 16);
        ulonglong2 t10 = __ldg(Fb1 + foff);
        ulonglong2 t11 = __ldg(Fb1 + foff + 8);
        ulonglong2 t12 = __ldg(Fb1 + foff + 16);

        // x: 4 channels at wp = 4wq + k, k = 0..5 (one 128B wavefront each)
        const ulonglong2* xr = Xu + kk * 36 + wq;
        ulonglong2 x0 = xr[0];
        ulonglong2 x1 = xr[9];
        ulonglong2 x2 = xr[18];
        ulonglong2 x3 = xr[27];
        ulonglong2 x4 = xr[1];
        ulonglong2 x5 = xr[10];

        // filter even: pixel p uses x[p], x[p+1], x[p+2]
        UPD(a00, t00, x0); UPD(a00, t01, x1); UPD(a00, t02, x2);
        UPD(a01, t00, x1); UPD(a01, t01, x2); UPD(a01, t02, x3);
        UPD(a02, t00, x2); UPD(a02, t01, x3); UPD(a02, t02, x4);
        UPD(a03, t00, x3); UPD(a03, t01, x4); UPD(a03, t02, x5);
        // filter odd
        UPD(a10, t10, x0); UPD(a10, t11, x1); UPD(a10, t12, x2);
        UPD(a11, t10, x1); UPD(a11, t11, x2); UPD(a11, t12, x3);
        UPD(a12, t10, x2); UPD(a12, t11, x3); UPD(a12, t12, x4);
        UPD(a13, t10, x3); UPD(a13, t11, x4); UPD(a13, t12, x5);
    }

    // ---- Epilogue: horizontal add of packed lanes, float2 store per pixel ----
    const u64 ae[4] = {a00, a01, a02, a03};
    const u64 ao[4] = {a10, a11, a12, a13};
    #pragma unroll
    for (int p = 0; p < 4; p++) {
        u64 e = ae[p], o = ao[p];
        float r0 = __uint_as_float((unsigned)e) + __uint_as_float((unsigned)(e >> 32));
        float r1 = __uint_as_float((unsigned)o) + __uint_as_float((unsigned)(o >> 32));
        *reinterpret_cast<float2*>(
            out + ((nh * 32) + 4 * wq + p) * 64 + fbase + 2 * fp) = make_float2(r0, r1);
    }
}

extern "C" void kernel_launch(void* const* d_in, const int* in_sizes, int n_in,
                              void* d_out, int out_size) {
    const float* X = (const float*)d_in[0];
    const float* Fw = (const float*)d_in[1];
    float* out = (float*)d_out;

    cudaFuncSetAttribute(adder_layer_kernel,
                         cudaFuncAttributeMaxDynamicSharedMemorySize, SMEM_BYTES);
    dim3 grid(256, 4);
    adder_layer_kernel<<<grid, 64, SMEM_BYTES>>>(X, Fw, out);
}